// round 2
// baseline (speedup 1.0000x reference)
#include <cuda_runtime.h>

#define HEADS 12
#define DHEAD 64
#define DIN   768
#define DOUT  768
#define BATCH 8
#define SEQ   1024
#define BH    (BATCH * HEADS)      /* 96  */
#define ROWS  (BATCH * SEQ)        /* 8192 */

// ---------------- scratch (static device globals; no runtime allocation) ----
__device__ float g_q[BH * SEQ * DHEAD];   // [bh][n][d]  25 MB
__device__ float g_k[BH * SEQ * DHEAD];   // [bh][n][d]  25 MB
__device__ float g_v[BH * SEQ * DHEAD];   // [bh][n][d]  25 MB
__device__ float g_y[ROWS * DOUT];        // [b*n][h*64+d] 25 MB

// ============================================================================
// Tiled SGEMM: C[M x NC] = A[M x 768] * B[768 x NC] + bias
// BM=BN=128, BK=16, 256 threads, 8x8 per thread (split 4+4 strided by 64 to
// keep smem float4 reads conflict-free).
// MODE 0: A = x, scatter into g_q/g_k/g_v (qkv layout transform fused)
// MODE 1: A = g_y, plain store into `out`
// ============================================================================
template<int NC, int MODE>
__global__ __launch_bounds__(256)
void sgemm_kernel(const float* __restrict__ A,
                  const float* __restrict__ Bm,
                  const float* __restrict__ bias,
                  float* __restrict__ out)
{
    __shared__ float As[16][128];
    __shared__ float Bs[16][128];

    const int tid = threadIdx.x;
    const int bx = blockIdx.x, by = blockIdx.y;
    const int threadRow = tid >> 4;   // 0..15
    const int threadCol = tid & 15;   // 0..15

    // load mappings
    const int aRow = tid >> 2;            // 0..63
    const int aCol = (tid & 3) << 2;      // 0,4,8,12
    const int bRow = tid >> 5;            // 0..7
    const int bCol = (tid & 31) << 2;     // 0..124

    const float* Aeff = (MODE == 0) ? A : (const float*)g_y;
    const float* Ab = Aeff + (size_t)(by * 128) * DIN;
    const float* Bb = Bm + bx * 128;

    float acc[8][8];
#pragma unroll
    for (int i = 0; i < 8; i++)
#pragma unroll
        for (int j = 0; j < 8; j++) acc[i][j] = 0.f;

    for (int kt = 0; kt < DIN; kt += 16) {
#pragma unroll
        for (int r = 0; r < 2; r++) {
            float4 v = *(const float4*)(Ab + (size_t)(aRow + r * 64) * DIN + kt + aCol);
            As[aCol + 0][aRow + r * 64] = v.x;
            As[aCol + 1][aRow + r * 64] = v.y;
            As[aCol + 2][aRow + r * 64] = v.z;
            As[aCol + 3][aRow + r * 64] = v.w;
        }
#pragma unroll
        for (int r = 0; r < 2; r++) {
            *(float4*)&Bs[bRow + r * 8][bCol] =
                *(const float4*)(Bb + (size_t)(kt + bRow + r * 8) * NC + bCol);
        }
        __syncthreads();

#pragma unroll
        for (int k = 0; k < 16; k++) {
            float ra[8], rb[8];
            *(float4*)&ra[0] = *(float4*)&As[k][threadRow * 4];
            *(float4*)&ra[4] = *(float4*)&As[k][64 + threadRow * 4];
            *(float4*)&rb[0] = *(float4*)&Bs[k][threadCol * 4];
            *(float4*)&rb[4] = *(float4*)&Bs[k][64 + threadCol * 4];
#pragma unroll
            for (int i = 0; i < 8; i++)
#pragma unroll
                for (int j = 0; j < 8; j++)
                    acc[i][j] = fmaf(ra[i], rb[j], acc[i][j]);
        }
        __syncthreads();
    }

    // epilogue
#pragma unroll
    for (int i = 0; i < 8; i++) {
        const int row = by * 128 + ((i >> 2) * 64) + threadRow * 4 + (i & 3);
#pragma unroll
        for (int j = 0; j < 8; j++) {
            const int col = bx * 128 + ((j >> 2) * 64) + threadCol * 4 + (j & 3);
            const float val = acc[i][j] + bias[col];
            if (MODE == 0) {
                const int b = row >> 10, n = row & 1023;
                const int which = col / 768;
                const int rem = col - which * 768;
                const int h = rem >> 6, d = rem & 63;
                float* p = (which == 0) ? g_q : (which == 1) ? g_k : g_v;
                p[(((size_t)(b * HEADS + h)) * SEQ + n) * DHEAD + d] = val;
            } else {
                out[(size_t)row * NC + col] = val;
            }
        }
    }
}

// ============================================================================
// Fused flash-style attention.
// Reference: scores[i,j] = k_i . q_j / 8, softmax over j, O = P @ V.
// So "query" role = K rows, "key" role = Q rows.
// Grid: (BH, SEQ/64). Block: 256 threads, ty=tid/16 (i), tx=tid&15 (j / d).
// Strided column mappings (tx + 16*idx) -> conflict-free smem reads at pad 65.
// ============================================================================
#define PADW 65

__global__ __launch_bounds__(256)
void attn_kernel()
{
    extern __shared__ float sm[];
    float (*Ks)[PADW] = (float(*)[PADW])(sm);
    float (*Qs)[PADW] = (float(*)[PADW])(sm + 64 * PADW);
    float (*Vs)[PADW] = (float(*)[PADW])(sm + 2 * 64 * PADW);
    float (*Ps)[PADW] = (float(*)[PADW])(sm + 3 * 64 * PADW);

    const int bh = blockIdx.x;            // 0..95
    const int it = blockIdx.y;            // 0..15
    const int b = bh / HEADS;
    const int h = bh - b * HEADS;
    const int tid = threadIdx.x;
    const int ty = tid >> 4;              // 0..15
    const int tx = tid & 15;              // 0..15

    const size_t base = (size_t)bh * SEQ * DHEAD;

    // load K tile (the "query" rows of this block)
    {
        const float* kp = g_k + base + (size_t)it * 64 * DHEAD;
        const int c = tx * 4;
        for (int r = ty; r < 64; r += 16) {
            float4 v = *(const float4*)(kp + r * DHEAD + c);
            Ks[r][c + 0] = v.x; Ks[r][c + 1] = v.y;
            Ks[r][c + 2] = v.z; Ks[r][c + 3] = v.w;
        }
    }
    __syncthreads();

    float m[4], l[4], acc[4][4];
#pragma unroll
    for (int i = 0; i < 4; i++) {
        m[i] = -1e30f; l[i] = 0.f;
#pragma unroll
        for (int d = 0; d < 4; d++) acc[i][d] = 0.f;
    }

    for (int jt = 0; jt < 16; jt++) {
        // load Q and V j-tiles
        {
            const float* qp = g_q + base + (size_t)jt * 64 * DHEAD;
            const float* vp = g_v + base + (size_t)jt * 64 * DHEAD;
            const int c = tx * 4;
            for (int r = ty; r < 64; r += 16) {
                float4 q4 = *(const float4*)(qp + r * DHEAD + c);
                float4 v4 = *(const float4*)(vp + r * DHEAD + c);
                Qs[r][c + 0] = q4.x; Qs[r][c + 1] = q4.y;
                Qs[r][c + 2] = q4.z; Qs[r][c + 3] = q4.w;
                Vs[r][c + 0] = v4.x; Vs[r][c + 1] = v4.y;
                Vs[r][c + 2] = v4.z; Vs[r][c + 3] = v4.w;
            }
        }
        __syncthreads();

        // S tile: rows i = ty*4+ii, cols j = tx + 16*jj
        float s[4][4];
#pragma unroll
        for (int i = 0; i < 4; i++)
#pragma unroll
            for (int j = 0; j < 4; j++) s[i][j] = 0.f;

#pragma unroll
        for (int d = 0; d < 64; d++) {
            float ka[4], qa[4];
#pragma unroll
            for (int i = 0; i < 4; i++) ka[i] = Ks[ty * 4 + i][d];
#pragma unroll
            for (int j = 0; j < 4; j++) qa[j] = Qs[tx + 16 * j][d];
#pragma unroll
            for (int i = 0; i < 4; i++)
#pragma unroll
                for (int j = 0; j < 4; j++)
                    s[i][j] = fmaf(ka[i], qa[j], s[i][j]);
        }

        // online softmax over j (full row = 16 lanes x 4 regs)
#pragma unroll
        for (int i = 0; i < 4; i++) {
            float rm = -1e30f;
#pragma unroll
            for (int j = 0; j < 4; j++) {
                s[i][j] *= 0.125f;           // 1/sqrt(64)
                rm = fmaxf(rm, s[i][j]);
            }
#pragma unroll
            for (int o = 1; o < 16; o <<= 1)
                rm = fmaxf(rm, __shfl_xor_sync(0xffffffffu, rm, o));
            const float mn = fmaxf(m[i], rm);
            const float corr = __expf(m[i] - mn);
            m[i] = mn;
            float ps = 0.f;
#pragma unroll
            for (int j = 0; j < 4; j++) {
                const float p = __expf(s[i][j] - mn);
                s[i][j] = p;
                ps += p;
            }
#pragma unroll
            for (int o = 1; o < 16; o <<= 1)
                ps += __shfl_xor_sync(0xffffffffu, ps, o);
            l[i] = l[i] * corr + ps;
#pragma unroll
            for (int d = 0; d < 4; d++) acc[i][d] *= corr;
#pragma unroll
            for (int j = 0; j < 4; j++)
                Ps[ty * 4 + i][tx + 16 * j] = s[i][j];
        }
        __syncthreads();

        // O += P @ V   (acc cols d = tx + 16*dd)
#pragma unroll
        for (int j = 0; j < 64; j++) {
            float va[4];
#pragma unroll
            for (int d = 0; d < 4; d++) va[d] = Vs[j][tx + 16 * d];
#pragma unroll
            for (int i = 0; i < 4; i++) {
                const float p = Ps[ty * 4 + i][j];
#pragma unroll
                for (int d = 0; d < 4; d++)
                    acc[i][d] = fmaf(p, va[d], acc[i][d]);
            }
        }
        __syncthreads();
    }

    // write normalized output into [b][n][h*64+d] layout for the out-proj GEMM
    float* yp = g_y + ((size_t)b * SEQ + it * 64) * DOUT + h * DHEAD;
#pragma unroll
    for (int i = 0; i < 4; i++) {
        const float inv = 1.f / l[i];
#pragma unroll
        for (int d = 0; d < 4; d++)
            yp[(size_t)(ty * 4 + i) * DOUT + tx + 16 * d] = acc[i][d] * inv;
    }
}

// ============================================================================
extern "C" void kernel_launch(void* const* d_in, const int* in_sizes, int n_in,
                              void* d_out, int out_size)
{
    const float* x     = (const float*)d_in[0];
    const float* w_qkv = (const float*)d_in[1];
    const float* b_qkv = (const float*)d_in[2];
    const float* w_out = (const float*)d_in[3];
    const float* b_out = (const float*)d_in[4];
    float* out = (float*)d_out;

    const int attn_smem = 4 * 64 * PADW * (int)sizeof(float);  // 66560 B
    cudaFuncSetAttribute(attn_kernel,
                         cudaFuncAttributeMaxDynamicSharedMemorySize, attn_smem);

    // 1) QKV projection + bias + layout scatter
    {
        dim3 grid(2304 / 128, ROWS / 128);   // 18 x 64
        sgemm_kernel<2304, 0><<<grid, 256>>>(x, w_qkv, b_qkv, nullptr);
    }

    // 2) fused attention
    {
        dim3 grid(BH, SEQ / 64);             // 96 x 16
        attn_kernel<<<grid, 256, attn_smem>>>();
    }

    // 3) output projection + bias
    {
        dim3 grid(DOUT / 128, ROWS / 128);   // 6 x 64
        sgemm_kernel<DOUT, 1><<<grid, 256>>>(nullptr, w_out, b_out, out);
    }
}

// round 3
// speedup vs baseline: 1.7798x; 1.7798x over previous
#include <cuda_runtime.h>

#define HEADS 12
#define DHEAD 64
#define DIN   768
#define DOUT  768
#define BATCH 8
#define SEQ   1024
#define BH    (BATCH * HEADS)      /* 96  */
#define ROWS  (BATCH * SEQ)        /* 8192 */

// ---------------- scratch (static device globals; no runtime allocation) ----
__device__ float g_q[BH * SEQ * DHEAD];   // [bh][n][d]
__device__ float g_k[BH * SEQ * DHEAD];   // [bh][n][d]
__device__ float g_v[BH * SEQ * DHEAD];   // [bh][n][d]
__device__ float g_y[ROWS * DOUT];        // [b*n][h*64+d]

// ---------------- helpers ---------------------------------------------------
__device__ __forceinline__ unsigned f2tf(float x) {
    unsigned r;
    asm("cvt.rna.tf32.f32 %0, %1;" : "=r"(r) : "f"(x));
    return r;
}

// m16n8k8 tf32 mma: A row-major, B col-major, fp32 accumulate
__device__ __forceinline__ void mma8(float* c, const unsigned* a, const unsigned* b) {
    asm volatile(
        "mma.sync.aligned.m16n8k8.row.col.f32.tf32.tf32.f32 "
        "{%0,%1,%2,%3}, {%4,%5,%6,%7}, {%8,%9}, {%0,%1,%2,%3};"
        : "+f"(c[0]), "+f"(c[1]), "+f"(c[2]), "+f"(c[3])
        : "r"(a[0]), "r"(a[1]), "r"(a[2]), "r"(a[3]), "r"(b[0]), "r"(b[1]));
}

// ============================================================================
// Projection GEMM via mma.sync tf32.
// C[M x NC] = A[M x 768] * B[768 x NC] + bias. BM=BN=128, BK=32, 256 threads,
// warps 2x4 -> each warp 64x32 (4 m-tiles x 4 n-tiles of m16n8k8).
// Smem pads: A stride 36 (bank = 4r+c, conflict-free), B stride 136 (8k+n).
// MODE 0: scatter into g_q/g_k/g_v.  MODE 1: A = g_y, store to out.
// ============================================================================
template<int NC, int MODE>
__global__ __launch_bounds__(256)
void mma_gemm(const float* __restrict__ A,
              const float* __restrict__ Bm,
              const float* __restrict__ bias,
              float* __restrict__ out)
{
    __shared__ unsigned As[128 * 36];
    __shared__ unsigned Bs[32 * 136];

    const int tid = threadIdx.x;
    const int bx = blockIdx.x, by = blockIdx.y;
    const int wid = tid >> 5, lane = tid & 31;
    const int wm = wid >> 2, wn = wid & 3;
    const int l4 = lane >> 2, lm4 = lane & 3;

    const float* Aeff = (MODE == 0) ? A : (const float*)g_y;
    const float* Ab = Aeff + (size_t)(by * 128) * DIN;
    const float* Bb = Bm + bx * 128;

    const int arow = tid >> 1, acb = (tid & 1) * 16;   // A: 2 thr/row, 16 cols each
    const int brow = tid >> 3, bcb = (tid & 7) * 16;   // B: 8 thr/row, 16 cols each

    float4 ra[4], rb[4];
    float acc[4][4][4];
#pragma unroll
    for (int mt = 0; mt < 4; mt++)
#pragma unroll
        for (int nt = 0; nt < 4; nt++)
#pragma unroll
            for (int r = 0; r < 4; r++) acc[mt][nt][r] = 0.f;

    // prologue: load tile 0
#pragma unroll
    for (int i = 0; i < 4; i++)
        ra[i] = *(const float4*)(Ab + (size_t)arow * DIN + acb + i * 4);
#pragma unroll
    for (int i = 0; i < 4; i++)
        rb[i] = *(const float4*)(Bb + (size_t)brow * NC + bcb + i * 4);
#pragma unroll
    for (int i = 0; i < 4; i++) {
        As[arow * 36 + acb + i * 4 + 0] = f2tf(ra[i].x);
        As[arow * 36 + acb + i * 4 + 1] = f2tf(ra[i].y);
        As[arow * 36 + acb + i * 4 + 2] = f2tf(ra[i].z);
        As[arow * 36 + acb + i * 4 + 3] = f2tf(ra[i].w);
    }
#pragma unroll
    for (int i = 0; i < 4; i++) {
        Bs[brow * 136 + bcb + i * 4 + 0] = f2tf(rb[i].x);
        Bs[brow * 136 + bcb + i * 4 + 1] = f2tf(rb[i].y);
        Bs[brow * 136 + bcb + i * 4 + 2] = f2tf(rb[i].z);
        Bs[brow * 136 + bcb + i * 4 + 3] = f2tf(rb[i].w);
    }
    __syncthreads();

    const int NK = DIN / 32;   // 24
    for (int kt = 0; kt < NK; kt++) {
        if (kt + 1 < NK) {
            const int ko = (kt + 1) * 32;
#pragma unroll
            for (int i = 0; i < 4; i++)
                ra[i] = *(const float4*)(Ab + (size_t)arow * DIN + ko + acb + i * 4);
#pragma unroll
            for (int i = 0; i < 4; i++)
                rb[i] = *(const float4*)(Bb + (size_t)(ko + brow) * NC + bcb + i * 4);
        }
        // compute current tile
#pragma unroll
        for (int ks = 0; ks < 4; ks++) {
            const int k0 = ks * 8;
            unsigned af[4][4], bf[4][2];
#pragma unroll
            for (int mt = 0; mt < 4; mt++) {
                const int r = wm * 64 + mt * 16 + l4;
                af[mt][0] = As[r * 36 + k0 + lm4];
                af[mt][1] = As[(r + 8) * 36 + k0 + lm4];
                af[mt][2] = As[r * 36 + k0 + 4 + lm4];
                af[mt][3] = As[(r + 8) * 36 + k0 + 4 + lm4];
            }
#pragma unroll
            for (int nt = 0; nt < 4; nt++) {
                const int nc = wn * 32 + nt * 8 + l4;
                bf[nt][0] = Bs[(k0 + lm4) * 136 + nc];
                bf[nt][1] = Bs[(k0 + 4 + lm4) * 136 + nc];
            }
#pragma unroll
            for (int mt = 0; mt < 4; mt++)
#pragma unroll
                for (int nt = 0; nt < 4; nt++)
                    mma8(acc[mt][nt], af[mt], bf[nt]);
        }
        __syncthreads();
        if (kt + 1 < NK) {
#pragma unroll
            for (int i = 0; i < 4; i++) {
                As[arow * 36 + acb + i * 4 + 0] = f2tf(ra[i].x);
                As[arow * 36 + acb + i * 4 + 1] = f2tf(ra[i].y);
                As[arow * 36 + acb + i * 4 + 2] = f2tf(ra[i].z);
                As[arow * 36 + acb + i * 4 + 3] = f2tf(ra[i].w);
            }
#pragma unroll
            for (int i = 0; i < 4; i++) {
                Bs[brow * 136 + bcb + i * 4 + 0] = f2tf(rb[i].x);
                Bs[brow * 136 + bcb + i * 4 + 1] = f2tf(rb[i].y);
                Bs[brow * 136 + bcb + i * 4 + 2] = f2tf(rb[i].z);
                Bs[brow * 136 + bcb + i * 4 + 3] = f2tf(rb[i].w);
            }
            __syncthreads();
        }
    }

    // epilogue
#pragma unroll
    for (int mt = 0; mt < 4; mt++) {
#pragma unroll
        for (int nt = 0; nt < 4; nt++) {
#pragma unroll
            for (int r = 0; r < 4; r++) {
                const int row = by * 128 + wm * 64 + mt * 16 + l4 + ((r >> 1) ? 8 : 0);
                const int col = bx * 128 + wn * 32 + nt * 8 + 2 * lm4 + (r & 1);
                const float val = acc[mt][nt][r] + bias[col];
                if (MODE == 0) {
                    const int b = row >> 10, n = row & 1023;
                    const int which = col / 768;
                    const int rem = col - which * 768;
                    const int h = rem >> 6, d = rem & 63;
                    float* p = (which == 0) ? g_q : (which == 1) ? g_k : g_v;
                    p[(((size_t)(b * HEADS + h)) * SEQ + n) * DHEAD + d] = val;
                } else {
                    out[(size_t)row * NC + col] = val;
                }
            }
        }
    }
}

// ============================================================================
// Fused flash attention via mma.sync tf32.
// Reference: scores[i,j] = k_i . q_j / 8, softmax over j, O = P @ V.
// Block: 256 thr / 8 warps (2x4). i-tile = 64 K-rows, j-tiles of 64.
// S mma:  A = K tile [i][d] (stride 68), B = Q^T [d][j] (stride 72).
// PV mma: A = P tile [i][j] (stride 68), B = V   [j][d] (stride 72).
// Warp owns S/O rows (wm*32 + mt*16 + l4 + 8*half) -> softmax state in regs.
// ============================================================================
__global__ __launch_bounds__(256)
void attn_mma()
{
    extern __shared__ float smf[];
    unsigned* Ks = (unsigned*)smf;            // 64*68
    unsigned* Qs = Ks + 64 * 68;              // [d][j], 64*72
    unsigned* Vs = Qs + 64 * 72;              // [j][d], 64*72
    unsigned* Ps = Vs + 64 * 72;              // 64*68
    float* rmax = (float*)(Ps + 64 * 68);     // [4][64]
    float* rsum = rmax + 256;                 // [4][64]
    float* lsm  = rsum + 256;                 // [64]

    const int it = blockIdx.x;                // 0..15 (fast: L2 reuse per head)
    const int bh = blockIdx.y;                // 0..95
    const int b = bh / HEADS, h = bh - b * HEADS;
    const int tid = threadIdx.x;
    const int wid = tid >> 5, lane = tid & 31;
    const int wm = wid >> 2, wn = wid & 3;
    const int l4 = lane >> 2, lm4 = lane & 3;
    const size_t base = (size_t)bh * SEQ * DHEAD;

    // stage K tile (tf32)
    {
        const float* kp = g_k + base + (size_t)it * 64 * DHEAD;
        for (int idx = tid; idx < 1024; idx += 256) {
            const int r = idx >> 4, c = (idx & 15) << 2;
            float4 v = *(const float4*)(kp + r * DHEAD + c);
            Ks[r * 68 + c + 0] = f2tf(v.x);
            Ks[r * 68 + c + 1] = f2tf(v.y);
            Ks[r * 68 + c + 2] = f2tf(v.z);
            Ks[r * 68 + c + 3] = f2tf(v.w);
        }
    }
    if (tid < 64) lsm[tid] = 0.f;

    float co[2][2][4];
    float m_run[2][2];
#pragma unroll
    for (int mt = 0; mt < 2; mt++) {
        m_run[mt][0] = -1e30f; m_run[mt][1] = -1e30f;
#pragma unroll
        for (int nt = 0; nt < 2; nt++)
#pragma unroll
            for (int r = 0; r < 4; r++) co[mt][nt][r] = 0.f;
    }

    for (int jt = 0; jt < 16; jt++) {
        __syncthreads();   // protect Qs/Vs/Ps/red from previous iter's readers
        // stage Q (transposed) and V
        {
            const float* qp = g_q + base + (size_t)jt * 64 * DHEAD;
            const float* vp = g_v + base + (size_t)jt * 64 * DHEAD;
            for (int idx = tid; idx < 1024; idx += 256) {
                const int r = idx >> 4, c = (idx & 15) << 2;
                float4 q4 = *(const float4*)(qp + r * DHEAD + c);
                float4 v4 = *(const float4*)(vp + r * DHEAD + c);
                Qs[(c + 0) * 72 + r] = f2tf(q4.x);
                Qs[(c + 1) * 72 + r] = f2tf(q4.y);
                Qs[(c + 2) * 72 + r] = f2tf(q4.z);
                Qs[(c + 3) * 72 + r] = f2tf(q4.w);
                Vs[r * 72 + c + 0] = f2tf(v4.x);
                Vs[r * 72 + c + 1] = f2tf(v4.y);
                Vs[r * 72 + c + 2] = f2tf(v4.z);
                Vs[r * 72 + c + 3] = f2tf(v4.w);
            }
        }
        __syncthreads();

        // ---- S = K * Q^T  (warp tile 32x16) ----
        float cs[2][2][4];
#pragma unroll
        for (int mt = 0; mt < 2; mt++)
#pragma unroll
            for (int nt = 0; nt < 2; nt++)
#pragma unroll
                for (int r = 0; r < 4; r++) cs[mt][nt][r] = 0.f;

#pragma unroll
        for (int ks = 0; ks < 8; ks++) {
            const int k0 = ks * 8;
            unsigned af[2][4], bf[2][2];
#pragma unroll
            for (int mt = 0; mt < 2; mt++) {
                const int r = wm * 32 + mt * 16 + l4;
                af[mt][0] = Ks[r * 68 + k0 + lm4];
                af[mt][1] = Ks[(r + 8) * 68 + k0 + lm4];
                af[mt][2] = Ks[r * 68 + k0 + 4 + lm4];
                af[mt][3] = Ks[(r + 8) * 68 + k0 + 4 + lm4];
            }
#pragma unroll
            for (int nt = 0; nt < 2; nt++) {
                const int n = wn * 16 + nt * 8 + l4;
                bf[nt][0] = Qs[(k0 + lm4) * 72 + n];
                bf[nt][1] = Qs[(k0 + 4 + lm4) * 72 + n];
            }
#pragma unroll
            for (int mt = 0; mt < 2; mt++)
#pragma unroll
                for (int nt = 0; nt < 2; nt++)
                    mma8(cs[mt][nt], af[mt], bf[nt]);
        }
#pragma unroll
        for (int mt = 0; mt < 2; mt++)
#pragma unroll
            for (int nt = 0; nt < 2; nt++)
#pragma unroll
                for (int r = 0; r < 4; r++) cs[mt][nt][r] *= 0.125f;

        // ---- row max (quad shuffle + cross-warp via smem) ----
        float mloc[2][2];
#pragma unroll
        for (int mt = 0; mt < 2; mt++)
#pragma unroll
            for (int hh = 0; hh < 2; hh++)
                mloc[mt][hh] = fmaxf(fmaxf(cs[mt][0][2 * hh], cs[mt][0][2 * hh + 1]),
                                     fmaxf(cs[mt][1][2 * hh], cs[mt][1][2 * hh + 1]));
#pragma unroll
        for (int o = 1; o < 4; o <<= 1)
#pragma unroll
            for (int mt = 0; mt < 2; mt++)
#pragma unroll
                for (int hh = 0; hh < 2; hh++)
                    mloc[mt][hh] = fmaxf(mloc[mt][hh],
                                         __shfl_xor_sync(0xffffffffu, mloc[mt][hh], o));
        if (lm4 == 0) {
#pragma unroll
            for (int mt = 0; mt < 2; mt++)
#pragma unroll
                for (int hh = 0; hh < 2; hh++)
                    rmax[wn * 64 + wm * 32 + mt * 16 + l4 + 8 * hh] = mloc[mt][hh];
        }
        __syncthreads();

        float mnew[2][2], corr[2][2];
#pragma unroll
        for (int mt = 0; mt < 2; mt++)
#pragma unroll
            for (int hh = 0; hh < 2; hh++) {
                const int row = wm * 32 + mt * 16 + l4 + 8 * hh;
                const float rm = fmaxf(fmaxf(rmax[row], rmax[64 + row]),
                                       fmaxf(rmax[128 + row], rmax[192 + row]));
                mnew[mt][hh] = fmaxf(m_run[mt][hh], rm);
                corr[mt][hh] = __expf(m_run[mt][hh] - mnew[mt][hh]);
                m_run[mt][hh] = mnew[mt][hh];
            }

        // ---- p = exp(s - m), store P (tf32), row sums, rescale O ----
        float sloc[2][2] = {{0.f, 0.f}, {0.f, 0.f}};
#pragma unroll
        for (int mt = 0; mt < 2; mt++)
#pragma unroll
            for (int nt = 0; nt < 2; nt++)
#pragma unroll
                for (int r = 0; r < 4; r++) {
                    const int hh = r >> 1;
                    const float p = __expf(cs[mt][nt][r] - mnew[mt][hh]);
                    sloc[mt][hh] += p;
                    const int row = wm * 32 + mt * 16 + l4 + 8 * hh;
                    const int col = wn * 16 + nt * 8 + 2 * lm4 + (r & 1);
                    Ps[row * 68 + col] = f2tf(p);
                    co[mt][nt][r] *= corr[mt][hh];
                }
#pragma unroll
        for (int o = 1; o < 4; o <<= 1)
#pragma unroll
            for (int mt = 0; mt < 2; mt++)
#pragma unroll
                for (int hh = 0; hh < 2; hh++)
                    sloc[mt][hh] += __shfl_xor_sync(0xffffffffu, sloc[mt][hh], o);
        if (lm4 == 0) {
#pragma unroll
            for (int mt = 0; mt < 2; mt++)
#pragma unroll
                for (int hh = 0; hh < 2; hh++)
                    rsum[wn * 64 + wm * 32 + mt * 16 + l4 + 8 * hh] = sloc[mt][hh];
        }
        __syncthreads();

        // owners (wn==0, lm4==0) update l in smem
        if (wn == 0 && lm4 == 0) {
#pragma unroll
            for (int mt = 0; mt < 2; mt++)
#pragma unroll
                for (int hh = 0; hh < 2; hh++) {
                    const int row = wm * 32 + mt * 16 + l4 + 8 * hh;
                    const float s4 = rsum[row] + rsum[64 + row] + rsum[128 + row] + rsum[192 + row];
                    lsm[row] = lsm[row] * corr[mt][hh] + s4;
                }
        }

        // ---- O += P * V ----
#pragma unroll
        for (int ks = 0; ks < 8; ks++) {
            const int k0 = ks * 8;
            unsigned af[2][4], bf[2][2];
#pragma unroll
            for (int mt = 0; mt < 2; mt++) {
                const int r = wm * 32 + mt * 16 + l4;
                af[mt][0] = Ps[r * 68 + k0 + lm4];
                af[mt][1] = Ps[(r + 8) * 68 + k0 + lm4];
                af[mt][2] = Ps[r * 68 + k0 + 4 + lm4];
                af[mt][3] = Ps[(r + 8) * 68 + k0 + 4 + lm4];
            }
#pragma unroll
            for (int nt = 0; nt < 2; nt++) {
                const int n = wn * 16 + nt * 8 + l4;
                bf[nt][0] = Vs[(k0 + lm4) * 72 + n];
                bf[nt][1] = Vs[(k0 + 4 + lm4) * 72 + n];
            }
#pragma unroll
            for (int mt = 0; mt < 2; mt++)
#pragma unroll
                for (int nt = 0; nt < 2; nt++)
                    mma8(co[mt][nt], af[mt], bf[nt]);
        }
    }
    __syncthreads();

    // epilogue: normalize and write to g_y[b][n][h*64+d]
    float inv[2][2];
#pragma unroll
    for (int mt = 0; mt < 2; mt++)
#pragma unroll
        for (int hh = 0; hh < 2; hh++)
            inv[mt][hh] = 1.f / lsm[wm * 32 + mt * 16 + l4 + 8 * hh];
#pragma unroll
    for (int mt = 0; mt < 2; mt++)
#pragma unroll
        for (int nt = 0; nt < 2; nt++)
#pragma unroll
            for (int r = 0; r < 4; r++) {
                const int hh = r >> 1;
                const int rowl = wm * 32 + mt * 16 + l4 + 8 * hh;
                const int n = it * 64 + rowl;
                const int d = wn * 16 + nt * 8 + 2 * lm4 + (r & 1);
                g_y[((size_t)b * SEQ + n) * DOUT + h * DHEAD + d] = co[mt][nt][r] * inv[mt][hh];
            }
}

// ============================================================================
extern "C" void kernel_launch(void* const* d_in, const int* in_sizes, int n_in,
                              void* d_out, int out_size)
{
    const float* x     = (const float*)d_in[0];
    const float* w_qkv = (const float*)d_in[1];
    const float* b_qkv = (const float*)d_in[2];
    const float* w_out = (const float*)d_in[3];
    const float* b_out = (const float*)d_in[4];
    float* out = (float*)d_out;

    const int attn_smem = (64 * 68 + 64 * 72 + 64 * 72 + 64 * 68 + 256 + 256 + 64)
                          * (int)sizeof(float);   // 73984 B
    cudaFuncSetAttribute(attn_mma,
                         cudaFuncAttributeMaxDynamicSharedMemorySize, attn_smem);

    // 1) QKV projection + bias + layout scatter
    {
        dim3 grid(2304 / 128, ROWS / 128);   // 18 x 64
        mma_gemm<2304, 0><<<grid, 256>>>(x, w_qkv, b_qkv, nullptr);
    }

    // 2) fused attention
    {
        dim3 grid(16, BH);                   // it fast -> L2 reuse of Q/V per head
        attn_mma<<<grid, 256, attn_smem>>>();
    }

    // 3) output projection + bias
    {
        dim3 grid(DOUT / 128, ROWS / 128);   // 6 x 64
        mma_gemm<DOUT, 1><<<grid, 256>>>(nullptr, w_out, b_out, out);
    }
}

// round 4
// speedup vs baseline: 2.5363x; 1.4250x over previous
#include <cuda_runtime.h>

#define HEADS 12
#define DHEAD 64
#define DIN   768
#define DOUT  768
#define BATCH 8
#define SEQ   1024
#define BH    (BATCH * HEADS)      /* 96  */
#define ROWS  (BATCH * SEQ)        /* 8192 */

// ---------------- scratch (static device globals; no runtime allocation) ----
__device__ float g_q[BH * SEQ * DHEAD];     // [bh][n][d]  (raw fp32 from epilogue)
__device__ float g_k[BH * SEQ * DHEAD];
__device__ float g_v[BH * SEQ * DHEAD];
__device__ float g_y[ROWS * DOUT];          // tf32-rounded by attention epilogue
__device__ float g_x[ROWS * DIN];           // tf32-rounded x
__device__ float g_wq[DIN * 3 * HEADS * DHEAD]; // tf32-rounded w_qkv
__device__ float g_wo[HEADS * DHEAD * DOUT];    // tf32-rounded w_out

// ---------------- helpers ---------------------------------------------------
__device__ __forceinline__ unsigned f2tf(float x) {
    unsigned r;
    asm("cvt.rna.tf32.f32 %0, %1;" : "=r"(r) : "f"(x));
    return r;
}

// m16n8k8 tf32 mma: A row-major, B col-major, fp32 accumulate
__device__ __forceinline__ void mma8(float* c, const unsigned* a, const unsigned* b) {
    asm volatile(
        "mma.sync.aligned.m16n8k8.row.col.f32.tf32.tf32.f32 "
        "{%0,%1,%2,%3}, {%4,%5,%6,%7}, {%8,%9}, {%0,%1,%2,%3};"
        : "+f"(c[0]), "+f"(c[1]), "+f"(c[2]), "+f"(c[3])
        : "r"(a[0]), "r"(a[1]), "r"(a[2]), "r"(a[3]), "r"(b[0]), "r"(b[1]));
}

__device__ __forceinline__ void cp16(float* dst, const float* src) {
    unsigned d = (unsigned)__cvta_generic_to_shared(dst);
    asm volatile("cp.async.ca.shared.global [%0], [%1], 16;" :: "r"(d), "l"(src));
}
__device__ __forceinline__ void cp_commit() {
    asm volatile("cp.async.commit_group;");
}
template<int N>
__device__ __forceinline__ void cp_wait() {
    asm volatile("cp.async.wait_group %0;" :: "n"(N));
}

// ---------------- prepass: round fp32 -> tf32 (rna) -------------------------
__global__ __launch_bounds__(256)
void round_tf32(const float* __restrict__ s, float* __restrict__ d, int n)
{
    const int i = (blockIdx.x * 256 + threadIdx.x) * 4;
    if (i < n) {
        float4 v = *(const float4*)(s + i);
        float4 o;
        o.x = __uint_as_float(f2tf(v.x));
        o.y = __uint_as_float(f2tf(v.y));
        o.z = __uint_as_float(f2tf(v.z));
        o.w = __uint_as_float(f2tf(v.w));
        *(float4*)(d + i) = o;
    }
}

// ============================================================================
// Projection GEMM: C[M x NC] = A[M x 768] * B[768 x NC] + bias.
// 128 threads, 4 warps (2x2), warp tile 64x64, BK=32, cp.async 2-stage.
// Operands pre-rounded to tf32 -> fragments are raw bit reinterpretation.
// Smem: As stride 36 (bank=4r+c), Bs stride 136 (bank=8k+n): conflict-free.
// MODE 0: A=g_x, scatter into g_q/g_k/g_v.  MODE 1: A=g_y, store to out.
// ============================================================================
#define GASZ (128 * 36)
#define GBSZ (32 * 136)
#define GSTG (GASZ + GBSZ)   /* words per stage */

template<int NC, int MODE>
__global__ __launch_bounds__(128)
void mma_gemm(const float* __restrict__ Bm,
              const float* __restrict__ bias,
              float* __restrict__ out)
{
    extern __shared__ float sm[];

    const int tid = threadIdx.x;
    const int bx = blockIdx.x, by = blockIdx.y;
    const int wid = tid >> 5, lane = tid & 31;
    const int wm = wid >> 1, wn = wid & 1;
    const int l4 = lane >> 2, lm4 = lane & 3;

    const float* Aeff = (MODE == 0) ? (const float*)g_x : (const float*)g_y;
    const float* Ab = Aeff + (size_t)(by * 128) * DIN;
    const float* Bb = Bm + bx * 128;

    const int ar = tid >> 3, ac = (tid & 7) * 4;     // A: 8 thr/row, 16 rows/pass
    const int br = tid >> 5, bc = (tid & 31) * 4;    // B: 32 thr/row, 4 rows/pass

    float acc[4][8][4];
#pragma unroll
    for (int mt = 0; mt < 4; mt++)
#pragma unroll
        for (int nt = 0; nt < 8; nt++)
#pragma unroll
            for (int r = 0; r < 4; r++) acc[mt][nt][r] = 0.f;

    // stage loader
    auto stage_load = [&](int s, int kt) {
        float* As = sm + s * GSTG;
        float* Bs = As + GASZ;
#pragma unroll
        for (int p = 0; p < 8; p++)
            cp16(&As[(ar + p * 16) * 36 + ac],
                 Ab + (size_t)(ar + p * 16) * DIN + kt * 32 + ac);
#pragma unroll
        for (int p = 0; p < 8; p++)
            cp16(&Bs[(br + p * 4) * 136 + bc],
                 Bb + (size_t)(kt * 32 + br + p * 4) * NC + bc);
        cp_commit();
    };

    stage_load(0, 0);

    const int NK = DIN / 32;   // 24
    for (int kt = 0; kt < NK; kt++) {
        if (kt + 1 < NK) {
            stage_load((kt + 1) & 1, kt + 1);
            cp_wait<1>();
        } else {
            cp_wait<0>();
        }
        __syncthreads();

        const unsigned* As = (const unsigned*)(sm + (kt & 1) * GSTG);
        const unsigned* Bs = As + GASZ;
#pragma unroll
        for (int ks = 0; ks < 4; ks++) {
            const int k0 = ks * 8;
            unsigned af[4][4], bf[8][2];
#pragma unroll
            for (int mt = 0; mt < 4; mt++) {
                const int r = wm * 64 + mt * 16 + l4;
                af[mt][0] = As[r * 36 + k0 + lm4];
                af[mt][1] = As[(r + 8) * 36 + k0 + lm4];
                af[mt][2] = As[r * 36 + k0 + 4 + lm4];
                af[mt][3] = As[(r + 8) * 36 + k0 + 4 + lm4];
            }
#pragma unroll
            for (int nt = 0; nt < 8; nt++) {
                const int nc = wn * 64 + nt * 8 + l4;
                bf[nt][0] = Bs[(k0 + lm4) * 136 + nc];
                bf[nt][1] = Bs[(k0 + 4 + lm4) * 136 + nc];
            }
#pragma unroll
            for (int mt = 0; mt < 4; mt++)
#pragma unroll
                for (int nt = 0; nt < 8; nt++)
                    mma8(acc[mt][nt], af[mt], bf[nt]);
        }
        __syncthreads();
    }

    // epilogue
#pragma unroll
    for (int mt = 0; mt < 4; mt++) {
#pragma unroll
        for (int nt = 0; nt < 8; nt++) {
#pragma unroll
            for (int r = 0; r < 4; r++) {
                const int row = by * 128 + wm * 64 + mt * 16 + l4 + ((r >> 1) ? 8 : 0);
                const int col = bx * 128 + wn * 64 + nt * 8 + 2 * lm4 + (r & 1);
                const float val = acc[mt][nt][r] + bias[col];
                if (MODE == 0) {
                    const int b = row >> 10, n = row & 1023;
                    const int which = col / 768;
                    const int rem = col - which * 768;
                    const int h = rem >> 6, d = rem & 63;
                    float* p = (which == 0) ? g_q : (which == 1) ? g_k : g_v;
                    p[(((size_t)(b * HEADS + h)) * SEQ + n) * DHEAD + d] = val;
                } else {
                    out[(size_t)row * NC + col] = val;
                }
            }
        }
    }
}

// ============================================================================
// Fused flash attention, tf32 mma. i-tile 128, j-tile 64.
// 256 threads / 8 warps as 4x2: warp S tile 32(i) x 32(j), O tile 32(i) x 32(d).
// Reference: scores[i,j] = k_i . q_j / 8, softmax over j, O = P @ V.
// ============================================================================
__global__ __launch_bounds__(256)
void attn_mma()
{
    extern __shared__ float smf[];
    unsigned* Ks = (unsigned*)smf;            // [128][68]
    unsigned* Qs = Ks + 128 * 68;             // [d=64][72]  (j cols)
    unsigned* Vs = Qs + 64 * 72;              // [j=64][72]  (d cols)
    unsigned* Ps = Vs + 64 * 72;              // [128][68]
    float* rmax = (float*)(Ps + 128 * 68);    // [2][128]
    float* rsum = rmax + 256;                 // [2][128]
    float* lsm  = rsum + 256;                 // [128]

    const int it = blockIdx.x;                // 0..7 (fast: L2 reuse per head)
    const int bh = blockIdx.y;                // 0..95
    const int b = bh / HEADS, h = bh - b * HEADS;
    const int tid = threadIdx.x;
    const int wid = tid >> 5, lane = tid & 31;
    const int wm = wid >> 1, wn = wid & 1;    // 4 x 2
    const int l4 = lane >> 2, lm4 = lane & 3;
    const size_t base = (size_t)bh * SEQ * DHEAD;

    // stage K tile (128 x 64), rounding to tf32
    {
        const float* kp = g_k + base + (size_t)it * 128 * DHEAD;
        for (int idx = tid; idx < 2048; idx += 256) {
            const int r = idx >> 4, c = (idx & 15) << 2;
            float4 v = *(const float4*)(kp + r * DHEAD + c);
            Ks[r * 68 + c + 0] = f2tf(v.x);
            Ks[r * 68 + c + 1] = f2tf(v.y);
            Ks[r * 68 + c + 2] = f2tf(v.z);
            Ks[r * 68 + c + 3] = f2tf(v.w);
        }
    }
    if (tid < 128) lsm[tid] = 0.f;

    float co[2][4][4];
    float m_run[2][2];
#pragma unroll
    for (int mt = 0; mt < 2; mt++) {
        m_run[mt][0] = -1e30f; m_run[mt][1] = -1e30f;
#pragma unroll
        for (int nt = 0; nt < 4; nt++)
#pragma unroll
            for (int r = 0; r < 4; r++) co[mt][nt][r] = 0.f;
    }

    for (int jt = 0; jt < 16; jt++) {
        __syncthreads();   // protect Qs/Vs/Ps/reductions from previous readers
        {
            const float* qp = g_q + base + (size_t)jt * 64 * DHEAD;
            const float* vp = g_v + base + (size_t)jt * 64 * DHEAD;
            for (int idx = tid; idx < 1024; idx += 256) {
                const int r = idx >> 4, c = (idx & 15) << 2;
                float4 q4 = *(const float4*)(qp + r * DHEAD + c);
                float4 v4 = *(const float4*)(vp + r * DHEAD + c);
                Qs[(c + 0) * 72 + r] = f2tf(q4.x);
                Qs[(c + 1) * 72 + r] = f2tf(q4.y);
                Qs[(c + 2) * 72 + r] = f2tf(q4.z);
                Qs[(c + 3) * 72 + r] = f2tf(q4.w);
                Vs[r * 72 + c + 0] = f2tf(v4.x);
                Vs[r * 72 + c + 1] = f2tf(v4.y);
                Vs[r * 72 + c + 2] = f2tf(v4.z);
                Vs[r * 72 + c + 3] = f2tf(v4.w);
            }
        }
        __syncthreads();

        // ---- S = K * Q^T  (warp tile 32x32) ----
        float cs[2][4][4];
#pragma unroll
        for (int mt = 0; mt < 2; mt++)
#pragma unroll
            for (int nt = 0; nt < 4; nt++)
#pragma unroll
                for (int r = 0; r < 4; r++) cs[mt][nt][r] = 0.f;

#pragma unroll
        for (int ks = 0; ks < 8; ks++) {
            const int k0 = ks * 8;
            unsigned af[2][4], bf[4][2];
#pragma unroll
            for (int mt = 0; mt < 2; mt++) {
                const int r = wm * 32 + mt * 16 + l4;
                af[mt][0] = Ks[r * 68 + k0 + lm4];
                af[mt][1] = Ks[(r + 8) * 68 + k0 + lm4];
                af[mt][2] = Ks[r * 68 + k0 + 4 + lm4];
                af[mt][3] = Ks[(r + 8) * 68 + k0 + 4 + lm4];
            }
#pragma unroll
            for (int nt = 0; nt < 4; nt++) {
                const int n = wn * 32 + nt * 8 + l4;
                bf[nt][0] = Qs[(k0 + lm4) * 72 + n];
                bf[nt][1] = Qs[(k0 + 4 + lm4) * 72 + n];
            }
#pragma unroll
            for (int mt = 0; mt < 2; mt++)
#pragma unroll
                for (int nt = 0; nt < 4; nt++)
                    mma8(cs[mt][nt], af[mt], bf[nt]);
        }
#pragma unroll
        for (int mt = 0; mt < 2; mt++)
#pragma unroll
            for (int nt = 0; nt < 4; nt++)
#pragma unroll
                for (int r = 0; r < 4; r++) cs[mt][nt][r] *= 0.125f;

        // ---- row max (quad shuffle + 2-warp smem reduction) ----
        float mloc[2][2];
#pragma unroll
        for (int mt = 0; mt < 2; mt++)
#pragma unroll
            for (int hh = 0; hh < 2; hh++) {
                float v = -1e30f;
#pragma unroll
                for (int nt = 0; nt < 4; nt++)
                    v = fmaxf(v, fmaxf(cs[mt][nt][2 * hh], cs[mt][nt][2 * hh + 1]));
                mloc[mt][hh] = v;
            }
#pragma unroll
        for (int o = 1; o < 4; o <<= 1)
#pragma unroll
            for (int mt = 0; mt < 2; mt++)
#pragma unroll
                for (int hh = 0; hh < 2; hh++)
                    mloc[mt][hh] = fmaxf(mloc[mt][hh],
                                         __shfl_xor_sync(0xffffffffu, mloc[mt][hh], o));
        if (lm4 == 0) {
#pragma unroll
            for (int mt = 0; mt < 2; mt++)
#pragma unroll
                for (int hh = 0; hh < 2; hh++)
                    rmax[wn * 128 + wm * 32 + mt * 16 + l4 + 8 * hh] = mloc[mt][hh];
        }
        __syncthreads();

        float mnew[2][2], corr[2][2];
#pragma unroll
        for (int mt = 0; mt < 2; mt++)
#pragma unroll
            for (int hh = 0; hh < 2; hh++) {
                const int row = wm * 32 + mt * 16 + l4 + 8 * hh;
                const float rm = fmaxf(rmax[row], rmax[128 + row]);
                mnew[mt][hh] = fmaxf(m_run[mt][hh], rm);
                corr[mt][hh] = __expf(m_run[mt][hh] - mnew[mt][hh]);
                m_run[mt][hh] = mnew[mt][hh];
            }

        // ---- p = exp(s-m), store P (tf32), row sums, rescale O ----
        float sloc[2][2] = {{0.f, 0.f}, {0.f, 0.f}};
#pragma unroll
        for (int mt = 0; mt < 2; mt++)
#pragma unroll
            for (int nt = 0; nt < 4; nt++)
#pragma unroll
                for (int r = 0; r < 4; r++) {
                    const int hh = r >> 1;
                    const float p = __expf(cs[mt][nt][r] - mnew[mt][hh]);
                    sloc[mt][hh] += p;
                    const int row = wm * 32 + mt * 16 + l4 + 8 * hh;
                    const int col = wn * 32 + nt * 8 + 2 * lm4 + (r & 1);
                    Ps[row * 68 + col] = f2tf(p);
                    co[mt][nt][r] *= corr[mt][hh];
                }
#pragma unroll
        for (int o = 1; o < 4; o <<= 1)
#pragma unroll
            for (int mt = 0; mt < 2; mt++)
#pragma unroll
                for (int hh = 0; hh < 2; hh++)
                    sloc[mt][hh] += __shfl_xor_sync(0xffffffffu, sloc[mt][hh], o);
        if (lm4 == 0) {
#pragma unroll
            for (int mt = 0; mt < 2; mt++)
#pragma unroll
                for (int hh = 0; hh < 2; hh++)
                    rsum[wn * 128 + wm * 32 + mt * 16 + l4 + 8 * hh] = sloc[mt][hh];
        }
        __syncthreads();

        if (wn == 0 && lm4 == 0) {
#pragma unroll
            for (int mt = 0; mt < 2; mt++)
#pragma unroll
                for (int hh = 0; hh < 2; hh++) {
                    const int row = wm * 32 + mt * 16 + l4 + 8 * hh;
                    lsm[row] = lsm[row] * corr[mt][hh] + rsum[row] + rsum[128 + row];
                }
        }

        // ---- O += P * V ----
#pragma unroll
        for (int ks = 0; ks < 8; ks++) {
            const int k0 = ks * 8;
            unsigned af[2][4], bf[4][2];
#pragma unroll
            for (int mt = 0; mt < 2; mt++) {
                const int r = wm * 32 + mt * 16 + l4;
                af[mt][0] = Ps[r * 68 + k0 + lm4];
                af[mt][1] = Ps[(r + 8) * 68 + k0 + lm4];
                af[mt][2] = Ps[r * 68 + k0 + 4 + lm4];
                af[mt][3] = Ps[(r + 8) * 68 + k0 + 4 + lm4];
            }
#pragma unroll
            for (int nt = 0; nt < 4; nt++) {
                const int n = wn * 32 + nt * 8 + l4;
                bf[nt][0] = Vs[(k0 + lm4) * 72 + n];
                bf[nt][1] = Vs[(k0 + 4 + lm4) * 72 + n];
            }
#pragma unroll
            for (int mt = 0; mt < 2; mt++)
#pragma unroll
                for (int nt = 0; nt < 4; nt++)
                    mma8(co[mt][nt], af[mt], bf[nt]);
        }
    }
    __syncthreads();

    // epilogue: normalize, round to tf32, write g_y[b][n][h*64+d]
    float inv[2][2];
#pragma unroll
    for (int mt = 0; mt < 2; mt++)
#pragma unroll
        for (int hh = 0; hh < 2; hh++)
            inv[mt][hh] = 1.f / lsm[wm * 32 + mt * 16 + l4 + 8 * hh];
#pragma unroll
    for (int mt = 0; mt < 2; mt++)
#pragma unroll
        for (int nt = 0; nt < 4; nt++)
#pragma unroll
            for (int r = 0; r < 4; r++) {
                const int hh = r >> 1;
                const int rowl = wm * 32 + mt * 16 + l4 + 8 * hh;
                const int n = it * 128 + rowl;
                const int d = wn * 32 + nt * 8 + 2 * lm4 + (r & 1);
                g_y[((size_t)b * SEQ + n) * DOUT + h * DHEAD + d] =
                    __uint_as_float(f2tf(co[mt][nt][r] * inv[mt][hh]));
            }
}

// ============================================================================
extern "C" void kernel_launch(void* const* d_in, const int* in_sizes, int n_in,
                              void* d_out, int out_size)
{
    const float* x     = (const float*)d_in[0];
    const float* w_qkv = (const float*)d_in[1];
    const float* b_qkv = (const float*)d_in[2];
    const float* w_out = (const float*)d_in[3];
    const float* b_out = (const float*)d_in[4];
    float* out = (float*)d_out;

    float* gx; float* gwq; float* gwo;
    cudaGetSymbolAddress((void**)&gx,  g_x);
    cudaGetSymbolAddress((void**)&gwq, g_wq);
    cudaGetSymbolAddress((void**)&gwo, g_wo);

    const int gemm_smem = 2 * GSTG * (int)sizeof(float);    // 71680 B
    const int attn_smem = (128 * 68 + 64 * 72 + 64 * 72 + 128 * 68 + 256 + 256 + 128)
                          * (int)sizeof(float);             // 109056 B
    cudaFuncSetAttribute(mma_gemm<2304, 0>,
                         cudaFuncAttributeMaxDynamicSharedMemorySize, gemm_smem);
    cudaFuncSetAttribute(mma_gemm<DOUT, 1>,
                         cudaFuncAttributeMaxDynamicSharedMemorySize, gemm_smem);
    cudaFuncSetAttribute(attn_mma,
                         cudaFuncAttributeMaxDynamicSharedMemorySize, attn_smem);

    // 0) pre-round operands to tf32
    round_tf32<<<(ROWS * DIN / 4 + 255) / 256, 256>>>(x, gx, ROWS * DIN);
    round_tf32<<<(DIN * 2304 / 4 + 255) / 256, 256>>>(w_qkv, gwq, DIN * 2304);
    round_tf32<<<(DIN * DOUT / 4 + 255) / 256, 256>>>(w_out, gwo, DIN * DOUT);

    // 1) QKV projection + bias + layout scatter
    {
        dim3 grid(2304 / 128, ROWS / 128);   // 18 x 64
        mma_gemm<2304, 0><<<grid, 128, gemm_smem>>>(gwq, b_qkv, nullptr);
    }

    // 2) fused attention
    {
        dim3 grid(8, BH);                    // it fast -> L2 reuse per head
        attn_mma<<<grid, 256, attn_smem>>>();
    }

    // 3) output projection + bias
    {
        dim3 grid(DOUT / 128, ROWS / 128);   // 6 x 64
        mma_gemm<DOUT, 1><<<grid, 128, gemm_smem>>>(gwo, b_out, out);
    }
}

// round 5
// speedup vs baseline: 2.9908x; 1.1792x over previous
#include <cuda_runtime.h>

#define HEADS 12
#define DHEAD 64
#define DIN   768
#define DOUT  768
#define BATCH 8
#define SEQ   1024
#define BH    (BATCH * HEADS)      /* 96  */
#define ROWS  (BATCH * SEQ)        /* 8192 */

// ---------------- scratch (static device globals; no runtime allocation) ----
__device__ float g_q[BH * SEQ * DHEAD];     // tf32-rounded by QKV epilogue
__device__ float g_k[BH * SEQ * DHEAD];     // tf32-rounded
__device__ float g_v[BH * SEQ * DHEAD];     // tf32-rounded
__device__ float g_y[ROWS * DOUT];          // tf32-rounded by attention epilogue
__device__ float g_x[ROWS * DIN];           // tf32-rounded x
__device__ float g_wq[DIN * 3 * HEADS * DHEAD]; // tf32-rounded w_qkv
__device__ float g_wo[HEADS * DHEAD * DOUT];    // tf32-rounded w_out

// ---------------- helpers ---------------------------------------------------
__device__ __forceinline__ unsigned f2tf(float x) {
    unsigned r;
    asm("cvt.rna.tf32.f32 %0, %1;" : "=r"(r) : "f"(x));
    return r;
}

// m16n8k8 tf32 mma: fragments per PTX layout, fp32 accumulate
__device__ __forceinline__ void mma8(float* c, const unsigned* a, const unsigned* b) {
    asm volatile(
        "mma.sync.aligned.m16n8k8.row.col.f32.tf32.tf32.f32 "
        "{%0,%1,%2,%3}, {%4,%5,%6,%7}, {%8,%9}, {%0,%1,%2,%3};"
        : "+f"(c[0]), "+f"(c[1]), "+f"(c[2]), "+f"(c[3])
        : "r"(a[0]), "r"(a[1]), "r"(a[2]), "r"(a[3]), "r"(b[0]), "r"(b[1]));
}

__device__ __forceinline__ void cp16(void* dst, const float* src) {
    unsigned d = (unsigned)__cvta_generic_to_shared(dst);
    asm volatile("cp.async.ca.shared.global [%0], [%1], 16;" :: "r"(d), "l"(src));
}
__device__ __forceinline__ void cp_commit() {
    asm volatile("cp.async.commit_group;");
}
template<int N>
__device__ __forceinline__ void cp_wait() {
    asm volatile("cp.async.wait_group %0;" :: "n"(N));
}

// ---------------- prepass: round fp32 -> tf32 (rna) -------------------------
__global__ __launch_bounds__(256)
void round_tf32(const float* __restrict__ s, float* __restrict__ d, int n)
{
    const int i = (blockIdx.x * 256 + threadIdx.x) * 4;
    if (i < n) {
        float4 v = *(const float4*)(s + i);
        float4 o;
        o.x = __uint_as_float(f2tf(v.x));
        o.y = __uint_as_float(f2tf(v.y));
        o.z = __uint_as_float(f2tf(v.z));
        o.w = __uint_as_float(f2tf(v.w));
        *(float4*)(d + i) = o;
    }
}

// ============================================================================
// Projection GEMM: C[M x NC] = A[M x 768] * B[768 x NC] + bias.
// 128 threads, 4 warps (2x2), warp tile 64x64, BK=32, cp.async 2-stage,
// single __syncthreads per k-iter.
// MODE 0: A=g_x, scatter tf32-rounded into g_q/g_k/g_v.  MODE 1: A=g_y -> out.
// ============================================================================
#define GASZ (128 * 36)
#define GBSZ (32 * 136)
#define GSTG (GASZ + GBSZ)

template<int NC, int MODE>
__global__ __launch_bounds__(128)
void mma_gemm(const float* __restrict__ Bm,
              const float* __restrict__ bias,
              float* __restrict__ out)
{
    extern __shared__ float sm[];

    const int tid = threadIdx.x;
    const int bx = blockIdx.x, by = blockIdx.y;
    const int wid = tid >> 5, lane = tid & 31;
    const int wm = wid >> 1, wn = wid & 1;
    const int l4 = lane >> 2, lm4 = lane & 3;

    const float* Aeff = (MODE == 0) ? (const float*)g_x : (const float*)g_y;
    const float* Ab = Aeff + (size_t)(by * 128) * DIN;
    const float* Bb = Bm + bx * 128;

    const int ar = tid >> 3, ac = (tid & 7) * 4;
    const int br = tid >> 5, bc = (tid & 31) * 4;

    float acc[4][8][4];
#pragma unroll
    for (int mt = 0; mt < 4; mt++)
#pragma unroll
        for (int nt = 0; nt < 8; nt++)
#pragma unroll
            for (int r = 0; r < 4; r++) acc[mt][nt][r] = 0.f;

    auto stage_load = [&](int s, int kt) {
        float* As = sm + s * GSTG;
        float* Bs = As + GASZ;
#pragma unroll
        for (int p = 0; p < 8; p++)
            cp16(&As[(ar + p * 16) * 36 + ac],
                 Ab + (size_t)(ar + p * 16) * DIN + kt * 32 + ac);
#pragma unroll
        for (int p = 0; p < 8; p++)
            cp16(&Bs[(br + p * 4) * 136 + bc],
                 Bb + (size_t)(kt * 32 + br + p * 4) * NC + bc);
        cp_commit();
    };

    stage_load(0, 0);

    const int NK = DIN / 32;   // 24
    for (int kt = 0; kt < NK; kt++) {
        cp_wait<0>();
        __syncthreads();
        if (kt + 1 < NK) stage_load((kt + 1) & 1, kt + 1);

        const unsigned* As = (const unsigned*)(sm + (kt & 1) * GSTG);
        const unsigned* Bs = As + GASZ;
#pragma unroll
        for (int ks = 0; ks < 4; ks++) {
            const int k0 = ks * 8;
            unsigned af[4][4], bf[8][2];
#pragma unroll
            for (int mt = 0; mt < 4; mt++) {
                const int r = wm * 64 + mt * 16 + l4;
                af[mt][0] = As[r * 36 + k0 + lm4];
                af[mt][1] = As[(r + 8) * 36 + k0 + lm4];
                af[mt][2] = As[r * 36 + k0 + 4 + lm4];
                af[mt][3] = As[(r + 8) * 36 + k0 + 4 + lm4];
            }
#pragma unroll
            for (int nt = 0; nt < 8; nt++) {
                const int nc = wn * 64 + nt * 8 + l4;
                bf[nt][0] = Bs[(k0 + lm4) * 136 + nc];
                bf[nt][1] = Bs[(k0 + 4 + lm4) * 136 + nc];
            }
#pragma unroll
            for (int mt = 0; mt < 4; mt++)
#pragma unroll
                for (int nt = 0; nt < 8; nt++)
                    mma8(acc[mt][nt], af[mt], bf[nt]);
        }
    }

    // epilogue
#pragma unroll
    for (int mt = 0; mt < 4; mt++) {
#pragma unroll
        for (int nt = 0; nt < 8; nt++) {
#pragma unroll
            for (int r = 0; r < 4; r++) {
                const int row = by * 128 + wm * 64 + mt * 16 + l4 + ((r >> 1) ? 8 : 0);
                const int col = bx * 128 + wn * 64 + nt * 8 + 2 * lm4 + (r & 1);
                const float val = acc[mt][nt][r] + bias[col];
                if (MODE == 0) {
                    const int b = row >> 10, n = row & 1023;
                    const int which = col / 768;
                    const int rem = col - which * 768;
                    const int h = rem >> 6, d = rem & 63;
                    float* p = (which == 0) ? g_q : (which == 1) ? g_k : g_v;
                    p[(((size_t)(b * HEADS + h)) * SEQ + n) * DHEAD + d] =
                        __uint_as_float(f2tf(val));
                } else {
                    out[(size_t)row * NC + col] = val;
                }
            }
        }
    }
}

// ============================================================================
// Fused flash attention, tf32 mma, warp-private rows.
// Reference: scores[i,j] = k_i . q_j / 8, softmax over j, O = P @ V.
// i-tile 128 (8 warps x 16 rows), j-tile 64, double-buffered cp.async Q/V.
// All staging row-major (B ".col" fragment == row-major Q/V read).
// Softmax: quad shuffles only; m/l in registers; P via warp-private smem.
// One __syncthreads per j-iter.
// ============================================================================
__global__ __launch_bounds__(256)
void attn_mma()
{
    extern __shared__ float smf[];
    unsigned* Ks = (unsigned*)smf;            // [128][68]
    unsigned* Qb = Ks + 128 * 68;             // 2 x [64][68]
    unsigned* Vb = Qb + 2 * 64 * 68;          // 2 x [64][72]
    unsigned* Ps = Vb + 2 * 64 * 72;          // [128][68], warp-private rows

    const int it = blockIdx.x;                // 0..7
    const int bh = blockIdx.y;                // 0..95
    const int b = bh / HEADS, h = bh - b * HEADS;
    const int tid = threadIdx.x;
    const int wid = tid >> 5, lane = tid & 31;
    const int l4 = lane >> 2, lm4 = lane & 3;
    const size_t base = (size_t)bh * SEQ * DHEAD;

    // stage K tile (128 x 64) + first Q/V tile via cp.async
    {
        const float* kp = g_k + base + (size_t)it * 128 * DHEAD;
        for (int c = tid; c < 2048; c += 256) {
            const int r = c >> 4, col = (c & 15) << 2;
            cp16(&Ks[r * 68 + col], kp + r * DHEAD + col);
        }
        const float* qp = g_q + base;
        const float* vp = g_v + base;
        for (int c = tid; c < 1024; c += 256) {
            const int r = c >> 4, col = (c & 15) << 2;
            cp16(&Qb[r * 68 + col], qp + r * DHEAD + col);
            cp16(&Vb[r * 72 + col], vp + r * DHEAD + col);
        }
        cp_commit();
    }

    const int r0 = wid * 16 + l4;             // this thread's S/O row (+8 pair)
    unsigned* Pw = Ps + (size_t)wid * 16 * 68;

    float m_run[2] = {-1e30f, -1e30f};
    float l_run[2] = {0.f, 0.f};
    float co[8][4];
#pragma unroll
    for (int nt = 0; nt < 8; nt++)
#pragma unroll
        for (int r = 0; r < 4; r++) co[nt][r] = 0.f;

    for (int jt = 0; jt < 16; jt++) {
        cp_wait<0>();
        __syncthreads();      // staged data visible; everyone done with jt-1
        if (jt + 1 < 16) {
            const float* qp = g_q + base + (size_t)(jt + 1) * 64 * DHEAD;
            const float* vp = g_v + base + (size_t)(jt + 1) * 64 * DHEAD;
            unsigned* Qn = Qb + ((jt + 1) & 1) * 64 * 68;
            unsigned* Vn = Vb + ((jt + 1) & 1) * 64 * 72;
            for (int c = tid; c < 1024; c += 256) {
                const int r = c >> 4, col = (c & 15) << 2;
                cp16(&Qn[r * 68 + col], qp + r * DHEAD + col);
                cp16(&Vn[r * 72 + col], vp + r * DHEAD + col);
            }
            cp_commit();
        }
        const unsigned* Qs = Qb + (jt & 1) * 64 * 68;
        const unsigned* Vs = Vb + (jt & 1) * 64 * 72;

        // ---- S = K * Q^T : warp tile 16 x 64 ----
        float cs[8][4];
#pragma unroll
        for (int nt = 0; nt < 8; nt++)
#pragma unroll
            for (int r = 0; r < 4; r++) cs[nt][r] = 0.f;

#pragma unroll
        for (int ks = 0; ks < 8; ks++) {
            const int k0 = ks * 8;
            unsigned af[4];
            af[0] = Ks[r0 * 68 + k0 + lm4];
            af[1] = Ks[(r0 + 8) * 68 + k0 + lm4];
            af[2] = Ks[r0 * 68 + k0 + 4 + lm4];
            af[3] = Ks[(r0 + 8) * 68 + k0 + 4 + lm4];
#pragma unroll
            for (int nt = 0; nt < 8; nt++) {
                unsigned bf[2];
                bf[0] = Qs[(nt * 8 + l4) * 68 + k0 + lm4];
                bf[1] = Qs[(nt * 8 + l4) * 68 + k0 + 4 + lm4];
                mma8(cs[nt], af, bf);
            }
        }

        // ---- softmax (rows r0, r0+8; reduction over quad lanes only) ----
        float rm[2] = {-1e30f, -1e30f};
#pragma unroll
        for (int nt = 0; nt < 8; nt++)
#pragma unroll
            for (int r = 0; r < 4; r++) {
                cs[nt][r] *= 0.125f;
                rm[r >> 1] = fmaxf(rm[r >> 1], cs[nt][r]);
            }
#pragma unroll
        for (int o = 1; o < 4; o <<= 1) {
            rm[0] = fmaxf(rm[0], __shfl_xor_sync(0xffffffffu, rm[0], o));
            rm[1] = fmaxf(rm[1], __shfl_xor_sync(0xffffffffu, rm[1], o));
        }
        float mnew[2], corr[2], sl[2];
#pragma unroll
        for (int hh = 0; hh < 2; hh++) {
            mnew[hh] = fmaxf(m_run[hh], rm[hh]);
            corr[hh] = __expf(m_run[hh] - mnew[hh]);
            m_run[hh] = mnew[hh];
            sl[hh] = 0.f;
        }
#pragma unroll
        for (int nt = 0; nt < 8; nt++) {
            float p0 = __expf(cs[nt][0] - mnew[0]);
            float p1 = __expf(cs[nt][1] - mnew[0]);
            float p2 = __expf(cs[nt][2] - mnew[1]);
            float p3 = __expf(cs[nt][3] - mnew[1]);
            sl[0] += p0 + p1;
            sl[1] += p2 + p3;
            // P pairs as 8B stores: conflict-free (banks 4*l4+2*lm4 per phase)
            uint2 v0 = make_uint2(f2tf(p0), f2tf(p1));
            uint2 v1 = make_uint2(f2tf(p2), f2tf(p3));
            *(uint2*)&Pw[l4 * 68 + nt * 8 + 2 * lm4] = v0;
            *(uint2*)&Pw[(l4 + 8) * 68 + nt * 8 + 2 * lm4] = v1;
#pragma unroll
            for (int r = 0; r < 4; r++) co[nt][r] *= corr[r >> 1];
        }
#pragma unroll
        for (int o = 1; o < 4; o <<= 1) {
            sl[0] += __shfl_xor_sync(0xffffffffu, sl[0], o);
            sl[1] += __shfl_xor_sync(0xffffffffu, sl[1], o);
        }
        l_run[0] = l_run[0] * corr[0] + sl[0];
        l_run[1] = l_run[1] * corr[1] + sl[1];

        __syncwarp();   // Pw writes visible within warp

        // ---- O += P * V : warp tile 16 x 64 ----
#pragma unroll
        for (int ks = 0; ks < 8; ks++) {
            const int k0 = ks * 8;
            unsigned af[4];
            af[0] = Pw[l4 * 68 + k0 + lm4];
            af[1] = Pw[(l4 + 8) * 68 + k0 + lm4];
            af[2] = Pw[l4 * 68 + k0 + 4 + lm4];
            af[3] = Pw[(l4 + 8) * 68 + k0 + 4 + lm4];
#pragma unroll
            for (int nt = 0; nt < 8; nt++) {
                unsigned bf[2];
                bf[0] = Vs[(k0 + lm4) * 72 + nt * 8 + l4];
                bf[1] = Vs[(k0 + 4 + lm4) * 72 + nt * 8 + l4];
                mma8(co[nt], af, bf);
            }
        }
        __syncwarp();   // Pw fully read before next iter's overwrite
    }

    // epilogue: normalize, round to tf32, write g_y[b][n][h*64+d]
    const float inv0 = 1.f / l_run[0];
    const float inv1 = 1.f / l_run[1];
#pragma unroll
    for (int nt = 0; nt < 8; nt++)
#pragma unroll
        for (int r = 0; r < 4; r++) {
            const int row = r0 + 8 * (r >> 1);
            const int n = it * 128 + row;
            const int d = nt * 8 + 2 * lm4 + (r & 1);
            const float inv = (r >> 1) ? inv1 : inv0;
            g_y[((size_t)b * SEQ + n) * DOUT + h * DHEAD + d] =
                __uint_as_float(f2tf(co[nt][r] * inv));
        }
}

// ============================================================================
extern "C" void kernel_launch(void* const* d_in, const int* in_sizes, int n_in,
                              void* d_out, int out_size)
{
    const float* x     = (const float*)d_in[0];
    const float* w_qkv = (const float*)d_in[1];
    const float* b_qkv = (const float*)d_in[2];
    const float* w_out = (const float*)d_in[3];
    const float* b_out = (const float*)d_in[4];
    float* out = (float*)d_out;

    float* gx; float* gwq; float* gwo;
    cudaGetSymbolAddress((void**)&gx,  g_x);
    cudaGetSymbolAddress((void**)&gwq, g_wq);
    cudaGetSymbolAddress((void**)&gwo, g_wo);

    const int gemm_smem = 2 * GSTG * (int)sizeof(float);    // 71680 B
    const int attn_smem = (128 * 68 + 2 * 64 * 68 + 2 * 64 * 72 + 128 * 68)
                          * (int)sizeof(float);             // 141312 B
    cudaFuncSetAttribute(mma_gemm<2304, 0>,
                         cudaFuncAttributeMaxDynamicSharedMemorySize, gemm_smem);
    cudaFuncSetAttribute(mma_gemm<DOUT, 1>,
                         cudaFuncAttributeMaxDynamicSharedMemorySize, gemm_smem);
    cudaFuncSetAttribute(attn_mma,
                         cudaFuncAttributeMaxDynamicSharedMemorySize, attn_smem);

    // 0) pre-round GEMM operands to tf32
    round_tf32<<<(ROWS * DIN / 4 + 255) / 256, 256>>>(x, gx, ROWS * DIN);
    round_tf32<<<(DIN * 2304 / 4 + 255) / 256, 256>>>(w_qkv, gwq, DIN * 2304);
    round_tf32<<<(DIN * DOUT / 4 + 255) / 256, 256>>>(w_out, gwo, DIN * DOUT);

    // 1) QKV projection + bias + tf32 round + layout scatter
    {
        dim3 grid(2304 / 128, ROWS / 128);   // 18 x 64
        mma_gemm<2304, 0><<<grid, 128, gemm_smem>>>(gwq, b_qkv, nullptr);
    }

    // 2) fused attention
    {
        dim3 grid(8, BH);
        attn_mma<<<grid, 256, attn_smem>>>();
    }

    // 3) output projection + bias
    {
        dim3 grid(DOUT / 128, ROWS / 128);   // 6 x 64
        mma_gemm<DOUT, 1><<<grid, 128, gemm_smem>>>(gwo, b_out, out);
    }
}

// round 8
// speedup vs baseline: 4.8833x; 1.6327x over previous
#include <cuda_runtime.h>
#include <cuda_fp16.h>
#include <cstdint>

#define HEADS 12
#define DHEAD 64
#define DIN   768
#define DOUT  768
#define BATCH 8
#define SEQ   1024
#define BH    (BATCH * HEADS)      /* 96  */
#define ROWS  (BATCH * SEQ)        /* 8192 */

// ---------------- scratch (static device globals; no runtime allocation) ----
__device__ __half g_q[BH * SEQ * DHEAD];       // fp16 from QKV epilogue
__device__ __half g_k[BH * SEQ * DHEAD];
__device__ __half g_v[BH * SEQ * DHEAD];
__device__ __half g_y[ROWS * DOUT];            // fp16 from attention epilogue
__device__ __half g_x[ROWS * DIN];             // fp16 x
__device__ __half g_wq[DIN * 3 * HEADS * DHEAD]; // w_qkv TRANSPOSED [2304][768]
__device__ __half g_wo[HEADS * DHEAD * DOUT];    // w_out  TRANSPOSED [768][768]

// ---------------- helpers ---------------------------------------------------
// m16n8k16 fp16 mma, fp32 accumulate. A row-major, B col-major.
__device__ __forceinline__ void mma16(float* c, const unsigned* a, const unsigned* b) {
    asm volatile(
        "mma.sync.aligned.m16n8k16.row.col.f32.f16.f16.f32 "
        "{%0,%1,%2,%3}, {%4,%5,%6,%7}, {%8,%9}, {%0,%1,%2,%3};"
        : "+f"(c[0]), "+f"(c[1]), "+f"(c[2]), "+f"(c[3])
        : "r"(a[0]), "r"(a[1]), "r"(a[2]), "r"(a[3]), "r"(b[0]), "r"(b[1]));
}

__device__ __forceinline__ void ldm_x2_t(unsigned& d0, unsigned& d1, uint32_t addr) {
    asm volatile("ldmatrix.sync.aligned.m8n8.x2.trans.shared.b16 {%0,%1}, [%2];"
                 : "=r"(d0), "=r"(d1) : "r"(addr));
}

__device__ __forceinline__ void cp16(void* dst, const void* src) {
    unsigned d = (unsigned)__cvta_generic_to_shared(dst);
    asm volatile("cp.async.ca.shared.global [%0], [%1], 16;" :: "r"(d), "l"(src));
}
__device__ __forceinline__ void cp_commit() { asm volatile("cp.async.commit_group;"); }
template<int N>
__device__ __forceinline__ void cp_wait() {
    asm volatile("cp.async.wait_group %0;" :: "n"(N));
}
__device__ __forceinline__ uint32_t smem_u32(const void* p) {
    return (uint32_t)__cvta_generic_to_shared(p);
}

// ---------------- prepass: fp32 -> fp16 -------------------------------------
__global__ __launch_bounds__(256)
void f2h_kernel(const float* __restrict__ s, __half* __restrict__ d, int n)
{
    const int i = (blockIdx.x * 256 + threadIdx.x) * 4;
    if (i < n) {
        float4 v = *(const float4*)(s + i);
        __half2* o = (__half2*)(d + i);
        o[0] = __floats2half2_rn(v.x, v.y);
        o[1] = __floats2half2_rn(v.z, v.w);
    }
}

// ---------------- prepass: transpose fp32[R][C] -> fp16[C][R] ---------------
template<int R, int C>
__global__ __launch_bounds__(256)
void transp_h(const float* __restrict__ in, __half* __restrict__ outp)
{
    __shared__ float t[32][33];
    const int bx = blockIdx.x, by = blockIdx.y;   // bx over C/32, by over R/32
    const int tx = threadIdx.x, ty = threadIdx.y;
    const int x = bx * 32 + tx;
#pragma unroll
    for (int i = ty; i < 32; i += 8)
        t[i][tx] = in[(size_t)(by * 32 + i) * C + x];
    __syncthreads();
    const int xr = by * 32 + tx;
#pragma unroll
    for (int i = ty; i < 32; i += 8)
        outp[(size_t)(bx * 32 + i) * R + xr] = __float2half_rn(t[tx][i]);
}

// ============================================================================
// Projection GEMM, fp16 m16n8k16: C[M x NC] = A[M x 768] * Wt^T + bias.
// 128 threads, 4 warps (2x2), warp tile 64x64, BM=BN=128, BK=64,
// cp.async double buffer, one __syncthreads per k-iter.
// Smem tiles [128][72] halfs (stride 72 -> conflict-free fragment loads).
// MODE 0: A=g_x, scatter fp16 into g_q/g_k/g_v.  MODE 1: A=g_y -> float out.
// ============================================================================
#define HSTG (2 * 128 * 72)   /* halfs per stage (A tile + B tile) */

template<int NC, int MODE>
__global__ __launch_bounds__(128)
void proj_h(const __half* __restrict__ Wt, const float* __restrict__ bias,
            float* __restrict__ outp)
{
    extern __shared__ __half smh[];

    const int tid = threadIdx.x;
    const int bx = blockIdx.x, by = blockIdx.y;
    const int wid = tid >> 5, lane = tid & 31;
    const int wm = wid >> 1, wn = wid & 1;
    const int l4 = lane >> 2, lm4 = lane & 3;

    const __half* Aeff = (MODE == 0) ? (const __half*)g_x : (const __half*)g_y;
    const __half* Ab = Aeff + (size_t)(by * 128) * DIN;
    const __half* Bb = Wt + (size_t)(bx * 128) * DIN;

    float acc[4][8][4];
#pragma unroll
    for (int mt = 0; mt < 4; mt++)
#pragma unroll
        for (int nt = 0; nt < 8; nt++)
#pragma unroll
            for (int r = 0; r < 4; r++) acc[mt][nt][r] = 0.f;

    auto stage_load = [&](int s, int kt) {
        __half* As = smh + s * HSTG;
        __half* Bs = As + 128 * 72;
        // 128 rows x 8 chunks (16B) each for A and B
        for (int idx = tid; idx < 1024; idx += 128) {
            const int r = idx >> 3, c8 = idx & 7;
            cp16(&As[r * 72 + c8 * 8], Ab + (size_t)r * DIN + kt * 64 + c8 * 8);
            cp16(&Bs[r * 72 + c8 * 8], Bb + (size_t)r * DIN + kt * 64 + c8 * 8);
        }
        cp_commit();
    };

    stage_load(0, 0);

    const int NK = DIN / 64;   // 12
    for (int kt = 0; kt < NK; kt++) {
        cp_wait<0>();
        __syncthreads();
        if (kt + 1 < NK) stage_load((kt + 1) & 1, kt + 1);

        const __half* As = smh + (kt & 1) * HSTG;
        const __half* Bs = As + 128 * 72;
#pragma unroll
        for (int ks = 0; ks < 4; ks++) {
            const int k0 = ks * 16;
            unsigned af[4][4], bf[8][2];
#pragma unroll
            for (int mt = 0; mt < 4; mt++) {
                const int r = wm * 64 + mt * 16 + l4;
                af[mt][0] = *(const unsigned*)&As[r * 72 + k0 + 2 * lm4];
                af[mt][1] = *(const unsigned*)&As[(r + 8) * 72 + k0 + 2 * lm4];
                af[mt][2] = *(const unsigned*)&As[r * 72 + k0 + 8 + 2 * lm4];
                af[mt][3] = *(const unsigned*)&As[(r + 8) * 72 + k0 + 8 + 2 * lm4];
            }
#pragma unroll
            for (int nt = 0; nt < 8; nt++) {
                const int n = wn * 64 + nt * 8 + l4;
                bf[nt][0] = *(const unsigned*)&Bs[n * 72 + k0 + 2 * lm4];
                bf[nt][1] = *(const unsigned*)&Bs[n * 72 + k0 + 8 + 2 * lm4];
            }
#pragma unroll
            for (int mt = 0; mt < 4; mt++)
#pragma unroll
                for (int nt = 0; nt < 8; nt++)
                    mma16(acc[mt][nt], af[mt], bf[nt]);
        }
    }

    // epilogue
#pragma unroll
    for (int mt = 0; mt < 4; mt++) {
#pragma unroll
        for (int nt = 0; nt < 8; nt++) {
#pragma unroll
            for (int r = 0; r < 4; r++) {
                const int row = by * 128 + wm * 64 + mt * 16 + l4 + ((r >> 1) ? 8 : 0);
                const int col = bx * 128 + wn * 64 + nt * 8 + 2 * lm4 + (r & 1);
                const float val = acc[mt][nt][r] + bias[col];
                if (MODE == 0) {
                    const int b = row >> 10, n = row & 1023;
                    const int which = col / 768;
                    const int rem = col - which * 768;
                    const int h = rem >> 6, d = rem & 63;
                    __half* p = (which == 0) ? g_q : (which == 1) ? g_k : g_v;
                    p[(((size_t)(b * HEADS + h)) * SEQ + n) * DHEAD + d] =
                        __float2half_rn(val);
                } else {
                    outp[(size_t)row * NC + col] = val;
                }
            }
        }
    }
}

// ============================================================================
// Fused flash attention, fp16 m16n8k16, warp-private rows.
// Reference: scores[i,j] = k_i . q_j / 8, softmax over j, O = P @ V.
// i-tile 128 (8 warps x 16 rows), j-tile 64, double-buffered cp.async Q/V.
// K/Q/P staged row-major stride 72 (conflict-free); V via ldmatrix.x2.trans.
// ============================================================================
__global__ __launch_bounds__(256)
void attn_h()
{
    extern __shared__ __half smh[];
    __half* Ks = smh;                      // [128][72]
    __half* Qb = Ks + 128 * 72;            // 2 x [64][72]
    __half* Vb = Qb + 2 * 64 * 72;         // 2 x [64][72]
    __half* Ps = Vb + 2 * 64 * 72;         // [128][72], warp-private rows

    const int it = blockIdx.x;             // 0..7
    const int bh = blockIdx.y;             // 0..95
    const int b = bh / HEADS, h = bh - b * HEADS;
    const int tid = threadIdx.x;
    const int wid = tid >> 5, lane = tid & 31;
    const int l4 = lane >> 2, lm4 = lane & 3;
    const size_t base = (size_t)bh * SEQ * DHEAD;

    // stage K tile (128x64) + first Q/V tiles
    {
        const __half* kp = g_k + base + (size_t)it * 128 * DHEAD;
        for (int c = tid; c < 1024; c += 256) {
            const int r = c >> 3, col = (c & 7) << 3;
            cp16(&Ks[r * 72 + col], kp + r * DHEAD + col);
        }
        const __half* qp = g_q + base;
        const __half* vp = g_v + base;
        for (int c = tid; c < 512; c += 256) {
            const int r = c >> 3, col = (c & 7) << 3;
            cp16(&Qb[r * 72 + col], qp + r * DHEAD + col);
            cp16(&Vb[r * 72 + col], vp + r * DHEAD + col);
        }
        cp_commit();
    }

    const int r0 = wid * 16 + l4;          // this thread's S/O rows (and +8)
    __half* Pw = Ps + wid * 16 * 72;

    float m_run[2] = {-1e30f, -1e30f};
    float l_run[2] = {0.f, 0.f};
    float co[8][4];
#pragma unroll
    for (int nt = 0; nt < 8; nt++)
#pragma unroll
        for (int r = 0; r < 4; r++) co[nt][r] = 0.f;

    for (int jt = 0; jt < 16; jt++) {
        cp_wait<0>();
        __syncthreads();
        if (jt + 1 < 16) {
            const __half* qp = g_q + base + (size_t)(jt + 1) * 64 * DHEAD;
            const __half* vp = g_v + base + (size_t)(jt + 1) * 64 * DHEAD;
            __half* Qn = Qb + ((jt + 1) & 1) * 64 * 72;
            __half* Vn = Vb + ((jt + 1) & 1) * 64 * 72;
            for (int c = tid; c < 512; c += 256) {
                const int r = c >> 3, col = (c & 7) << 3;
                cp16(&Qn[r * 72 + col], qp + r * DHEAD + col);
                cp16(&Vn[r * 72 + col], vp + r * DHEAD + col);
            }
            cp_commit();
        }
        const __half* Qs = Qb + (jt & 1) * 64 * 72;
        const __half* Vs = Vb + (jt & 1) * 64 * 72;

        // ---- S = K * Q^T : warp tile 16 x 64, K chunks of 16 ----
        float cs[8][4];
#pragma unroll
        for (int nt = 0; nt < 8; nt++)
#pragma unroll
            for (int r = 0; r < 4; r++) cs[nt][r] = 0.f;

#pragma unroll
        for (int ks = 0; ks < 4; ks++) {
            const int k0 = ks * 16;
            unsigned af[4];
            af[0] = *(const unsigned*)&Ks[r0 * 72 + k0 + 2 * lm4];
            af[1] = *(const unsigned*)&Ks[(r0 + 8) * 72 + k0 + 2 * lm4];
            af[2] = *(const unsigned*)&Ks[r0 * 72 + k0 + 8 + 2 * lm4];
            af[3] = *(const unsigned*)&Ks[(r0 + 8) * 72 + k0 + 8 + 2 * lm4];
#pragma unroll
            for (int nt = 0; nt < 8; nt++) {
                unsigned bf[2];
                bf[0] = *(const unsigned*)&Qs[(nt * 8 + l4) * 72 + k0 + 2 * lm4];
                bf[1] = *(const unsigned*)&Qs[(nt * 8 + l4) * 72 + k0 + 8 + 2 * lm4];
                mma16(cs[nt], af, bf);
            }
        }

        // ---- softmax (rows r0, r0+8; quad-lane reductions only) ----
        float rm[2] = {-1e30f, -1e30f};
#pragma unroll
        for (int nt = 0; nt < 8; nt++)
#pragma unroll
            for (int r = 0; r < 4; r++) {
                cs[nt][r] *= 0.125f;
                rm[r >> 1] = fmaxf(rm[r >> 1], cs[nt][r]);
            }
#pragma unroll
        for (int o = 1; o < 4; o <<= 1) {
            rm[0] = fmaxf(rm[0], __shfl_xor_sync(0xffffffffu, rm[0], o));
            rm[1] = fmaxf(rm[1], __shfl_xor_sync(0xffffffffu, rm[1], o));
        }
        float mnew[2], corr[2], sl[2];
#pragma unroll
        for (int hh = 0; hh < 2; hh++) {
            mnew[hh] = fmaxf(m_run[hh], rm[hh]);
            corr[hh] = __expf(m_run[hh] - mnew[hh]);
            m_run[hh] = mnew[hh];
            sl[hh] = 0.f;
        }
#pragma unroll
        for (int nt = 0; nt < 8; nt++) {
            float p0 = __expf(cs[nt][0] - mnew[0]);
            float p1 = __expf(cs[nt][1] - mnew[0]);
            float p2 = __expf(cs[nt][2] - mnew[1]);
            float p3 = __expf(cs[nt][3] - mnew[1]);
            sl[0] += p0 + p1;
            sl[1] += p2 + p3;
            // P cols nt*8 + 2*lm4, +1 are adjacent -> half2 stores, conflict-free
            *(__half2*)&Pw[l4 * 72 + nt * 8 + 2 * lm4] = __floats2half2_rn(p0, p1);
            *(__half2*)&Pw[(l4 + 8) * 72 + nt * 8 + 2 * lm4] = __floats2half2_rn(p2, p3);
#pragma unroll
            for (int r = 0; r < 4; r++) co[nt][r] *= corr[r >> 1];
        }
#pragma unroll
        for (int o = 1; o < 4; o <<= 1) {
            sl[0] += __shfl_xor_sync(0xffffffffu, sl[0], o);
            sl[1] += __shfl_xor_sync(0xffffffffu, sl[1], o);
        }
        l_run[0] = l_run[0] * corr[0] + sl[0];
        l_run[1] = l_run[1] * corr[1] + sl[1];

        __syncwarp();   // Pw writes visible within warp

        // ---- O += P * V : V B-fragments via ldmatrix.x2.trans ----
        const uint32_t vaddr = smem_u32(Vs + (lane & 15) * 72);
#pragma unroll
        for (int ks = 0; ks < 4; ks++) {
            const int k0 = ks * 16;
            unsigned af[4];
            af[0] = *(const unsigned*)&Pw[l4 * 72 + k0 + 2 * lm4];
            af[1] = *(const unsigned*)&Pw[(l4 + 8) * 72 + k0 + 2 * lm4];
            af[2] = *(const unsigned*)&Pw[l4 * 72 + k0 + 8 + 2 * lm4];
            af[3] = *(const unsigned*)&Pw[(l4 + 8) * 72 + k0 + 8 + 2 * lm4];
#pragma unroll
            for (int nt = 0; nt < 8; nt++) {
                unsigned bf0, bf1;
                ldm_x2_t(bf0, bf1, vaddr + k0 * 144 + nt * 16);
                unsigned bf[2] = {bf0, bf1};
                mma16(co[nt], af, bf);
            }
        }
        __syncwarp();   // Pw fully read before next iter's overwrite
    }

    // epilogue: normalize, write fp16 g_y[b][n][h*64+d]
    const float inv0 = 1.f / l_run[0];
    const float inv1 = 1.f / l_run[1];
#pragma unroll
    for (int nt = 0; nt < 8; nt++)
#pragma unroll
        for (int r = 0; r < 4; r++) {
            const int row = r0 + 8 * (r >> 1);
            const int n = it * 128 + row;
            const int d = nt * 8 + 2 * lm4 + (r & 1);
            const float inv = (r >> 1) ? inv1 : inv0;
            g_y[((size_t)b * SEQ + n) * DOUT + h * DHEAD + d] =
                __float2half_rn(co[nt][r] * inv);
        }
}

// ============================================================================
extern "C" void kernel_launch(void* const* d_in, const int* in_sizes, int n_in,
                              void* d_out, int out_size)
{
    const float* x     = (const float*)d_in[0];
    const float* w_qkv = (const float*)d_in[1];
    const float* b_qkv = (const float*)d_in[2];
    const float* w_out = (const float*)d_in[3];
    const float* b_out = (const float*)d_in[4];
    float* out = (float*)d_out;

    __half* gx; __half* gwq; __half* gwo;
    cudaGetSymbolAddress((void**)&gx,  g_x);
    cudaGetSymbolAddress((void**)&gwq, g_wq);
    cudaGetSymbolAddress((void**)&gwo, g_wo);

    const int gemm_smem = 2 * HSTG * (int)sizeof(__half);   // 73728 B
    const int attn_smem = (128 * 72 + 2 * 64 * 72 + 2 * 64 * 72 + 128 * 72)
                          * (int)sizeof(__half);            // 73728 B
    cudaFuncSetAttribute(proj_h<2304, 0>,
                         cudaFuncAttributeMaxDynamicSharedMemorySize, gemm_smem);
    cudaFuncSetAttribute(proj_h<DOUT, 1>,
                         cudaFuncAttributeMaxDynamicSharedMemorySize, gemm_smem);
    cudaFuncSetAttribute(attn_h,
                         cudaFuncAttributeMaxDynamicSharedMemorySize, attn_smem);

    // 0) prepass: x -> fp16; weights -> transposed fp16 [N][K]
    f2h_kernel<<<(ROWS * DIN / 4 + 255) / 256, 256>>>(x, gx, ROWS * DIN);
    {
        dim3 blk(32, 8);
        transp_h<DIN, 2304><<<dim3(2304 / 32, DIN / 32), blk>>>(w_qkv, gwq);
        transp_h<DIN, DOUT><<<dim3(DOUT / 32, DIN / 32), blk>>>(w_out, gwo);
    }

    // 1) QKV projection + bias + fp16 scatter
    {
        dim3 grid(2304 / 128, ROWS / 128);   // 18 x 64
        proj_h<2304, 0><<<grid, 128, gemm_smem>>>(gwq, b_qkv, nullptr);
    }

    // 2) fused attention
    {
        dim3 grid(8, BH);
        attn_h<<<grid, 256, attn_smem>>>();
    }

    // 3) output projection + bias (fp32 out)
    {
        dim3 grid(DOUT / 128, ROWS / 128);   // 6 x 64
        proj_h<DOUT, 1><<<grid, 128, gemm_smem>>>(gwo, b_out, out);
    }
}